// round 1
// baseline (speedup 1.0000x reference)
#include <cuda_runtime.h>
#include <cuda_bf16.h>

// Problem constants
#define D_DIA   128
#define L_DIA   40
#define NDIM    512
#define NHID    512
#define NUM_K   4
#define N_UTT   (D_DIA * L_DIA)        // 5120
#define N_NODE  (3 * N_UTT)            // 15360
#define ROWS_PER_DIA (3 * L_DIA)       // 120
#define OUT_D2  (NDIM + 2 * NHID)      // 1536
#define OUT_COLS (3 * OUT_D2)          // 4608

// Scratch buffers (device globals; no runtime allocation allowed)
__device__ float g_feats[N_NODE * NDIM];
__device__ float g_x1   [N_NODE * NHID];
__device__ float g_bufA [N_NODE * NHID];
__device__ float g_bufB [N_NODE * NHID];
__device__ float g_agg  [N_NODE * NHID];

// ---------------------------------------------------------------------------
// Build node features: per dialogue the node order is [l block, a block, v block].
// l gets speaker embedding added (spk chosen by argmax over qmask[t, dia, 0:2]).
// ---------------------------------------------------------------------------
__global__ void build_feats_kernel(const float* __restrict__ a,
                                   const float* __restrict__ v,
                                   const float* __restrict__ l,
                                   const float* __restrict__ qmask,
                                   const float* __restrict__ spk)
{
    int idx = blockIdx.x * blockDim.x + threadIdx.x;   // over N_NODE*NDIM
    if (idx >= N_NODE * NDIM) return;
    int c    = idx & (NDIM - 1);
    int node = idx >> 9;
    int dia  = node / ROWS_PER_DIA;
    int r    = node - dia * ROWS_PER_DIA;
    int m    = r / L_DIA;
    int t    = r - m * L_DIA;
    int u    = dia * L_DIA + t;

    float val;
    if (m == 0) {
        // qmask layout: [L_DIA, D_DIA, 2]
        float q0 = qmask[(t * D_DIA + dia) * 2 + 0];
        float q1 = qmask[(t * D_DIA + dia) * 2 + 1];
        int s = (q1 > q0) ? 1 : 0;   // argmax with first-index tie-break
        val = l[u * NDIM + c] + spk[s * NDIM + c];
    } else if (m == 1) {
        val = a[u * NDIM + c];
    } else {
        val = v[u * NDIM + c];
    }
    g_feats[idx] = val;
}

// ---------------------------------------------------------------------------
// Closed-form GCN aggregation:
//   agg[dia,m,t] = (S[dia,m] + T[dia,t] - x[dia,m,t]) / 42
// S = sum over t within modality block, T = sum over modalities at time t.
// ---------------------------------------------------------------------------
__global__ void agg_kernel(const float* __restrict__ x, float* __restrict__ out)
{
    int dia = blockIdx.x;
    int c   = blockIdx.y * 128 + threadIdx.x;
    const float* xb = x + (size_t)dia * ROWS_PER_DIA * NHID;
    float*       ob = out + (size_t)dia * ROWS_PER_DIA * NHID;

    float S0 = 0.f, S1 = 0.f, S2 = 0.f;
    #pragma unroll 4
    for (int t = 0; t < L_DIA; t++) S0 += xb[t * NHID + c];
    #pragma unroll 4
    for (int t = 0; t < L_DIA; t++) S1 += xb[(L_DIA + t) * NHID + c];
    #pragma unroll 4
    for (int t = 0; t < L_DIA; t++) S2 += xb[(2 * L_DIA + t) * NHID + c];

    const float inv = 1.0f / 42.0f;
    for (int t = 0; t < L_DIA; t++) {
        float x0 = xb[t * NHID + c];
        float x1 = xb[(L_DIA + t) * NHID + c];
        float x2 = xb[(2 * L_DIA + t) * NHID + c];
        float T = x0 + x1 + x2;
        ob[t * NHID + c]               = (S0 + T - x0) * inv;
        ob[(L_DIA + t) * NHID + c]     = (S1 + T - x1) * inv;
        ob[(2 * L_DIA + t) * NHID + c] = (S2 + T - x2) * inv;
    }
}

// ---------------------------------------------------------------------------
// SGEMM: C = A[M,K] * B[K,N] + bias (+ P residual).  M=15360, N=K=512.
// 128x128 block tile, BK=8, 256 threads, 8x8 per thread.
// ---------------------------------------------------------------------------
__global__ __launch_bounds__(256, 2)
void sgemm_kernel(const float* __restrict__ A, const float* __restrict__ B,
                  const float* __restrict__ bias, const float* __restrict__ P,
                  float* __restrict__ C)
{
    const int K = NHID, N = NHID;
    __shared__ float As[8][128];
    __shared__ float Bs[8][128];

    int bm  = blockIdx.y * 128;
    int bn  = blockIdx.x * 128;
    int tid = threadIdx.x;

    int arow  = tid >> 1;           // 0..127
    int acol4 = (tid & 1) * 4;      // 0 or 4
    int brow  = tid >> 5;           // 0..7
    int bcol  = (tid & 31) * 4;     // 0..124

    int tx = (tid & 15) * 8;        // col offset inside tile
    int ty = (tid >> 4) * 8;        // row offset inside tile

    float acc[8][8];
    #pragma unroll
    for (int i = 0; i < 8; i++)
        #pragma unroll
        for (int j = 0; j < 8; j++) acc[i][j] = 0.f;

    const float* Aptr = A + (size_t)(bm + arow) * K + acol4;
    const float* Bptr = B + (size_t)brow * N + bn + bcol;

    for (int k0 = 0; k0 < K; k0 += 8) {
        float4 av = *(const float4*)(Aptr + k0);
        As[acol4 + 0][arow] = av.x;
        As[acol4 + 1][arow] = av.y;
        As[acol4 + 2][arow] = av.z;
        As[acol4 + 3][arow] = av.w;
        *(float4*)&Bs[brow][bcol] = *(const float4*)(Bptr + (size_t)k0 * N);
        __syncthreads();

        #pragma unroll
        for (int k = 0; k < 8; k++) {
            float4 a0 = *(const float4*)&As[k][ty];
            float4 a1 = *(const float4*)&As[k][ty + 4];
            float4 b0 = *(const float4*)&Bs[k][tx];
            float4 b1 = *(const float4*)&Bs[k][tx + 4];
            float ar[8] = {a0.x, a0.y, a0.z, a0.w, a1.x, a1.y, a1.z, a1.w};
            float br[8] = {b0.x, b0.y, b0.z, b0.w, b1.x, b1.y, b1.z, b1.w};
            #pragma unroll
            for (int i = 0; i < 8; i++)
                #pragma unroll
                for (int j = 0; j < 8; j++)
                    acc[i][j] = fmaf(ar[i], br[j], acc[i][j]);
        }
        __syncthreads();
    }

    // Epilogue: + bias, optional residual add, store
    #pragma unroll
    for (int i = 0; i < 8; i++) {
        size_t row = (size_t)(bm + ty + i);
        #pragma unroll
        for (int j4 = 0; j4 < 8; j4 += 4) {
            int col = bn + tx + j4;
            float4 r;
            r.x = acc[i][j4 + 0] + bias[col + 0];
            r.y = acc[i][j4 + 1] + bias[col + 1];
            r.z = acc[i][j4 + 2] + bias[col + 2];
            r.w = acc[i][j4 + 3] + bias[col + 3];
            if (P != nullptr) {
                float4 p = *(const float4*)(P + row * N + col);
                r.x += p.x; r.y += p.y; r.z += p.z; r.w += p.w;
            }
            *(float4*)(C + row * N + col) = r;
        }
    }
}

// ---------------------------------------------------------------------------
// Assemble output: out1[u, m*1536 + {feats|x1|gnn}] for node (dia,m,t), u=dia*40+t
// ---------------------------------------------------------------------------
__global__ void assemble_kernel(const float* __restrict__ feats,
                                const float* __restrict__ x1,
                                const float* __restrict__ gnn,
                                float* __restrict__ out)
{
    int idx = blockIdx.x * blockDim.x + threadIdx.x;   // over N_NODE*NDIM
    if (idx >= N_NODE * NDIM) return;
    int c    = idx & (NDIM - 1);
    int node = idx >> 9;
    int dia  = node / ROWS_PER_DIA;
    int r    = node - dia * ROWS_PER_DIA;
    int m    = r / L_DIA;
    int t    = r - m * L_DIA;
    int u    = dia * L_DIA + t;

    float* o = out + (size_t)u * OUT_COLS + m * OUT_D2 + c;
    o[0]        = feats[idx];
    o[NDIM]     = x1[idx];
    o[2 * NHID] = gnn[idx];
}

// ---------------------------------------------------------------------------
extern "C" void kernel_launch(void* const* d_in, const int* in_sizes, int n_in,
                              void* d_out, int out_size)
{
    const float* a      = (const float*)d_in[0];
    const float* v      = (const float*)d_in[1];
    const float* l      = (const float*)d_in[2];
    const float* qmask  = (const float*)d_in[3];
    const float* spk    = (const float*)d_in[4];
    const float* fc1_W  = (const float*)d_in[5];
    const float* fc1_b  = (const float*)d_in[6];
    const float* convW  = (const float*)d_in[7];
    const float* convb  = (const float*)d_in[8];
    // d_in[9]=dia_len (uniform 40), [10]=epoch, [11]=src, [12]=dst: unused
    float* out = (float*)d_out;

    float* feats = nullptr, *x1 = nullptr, *bufA = nullptr, *bufB = nullptr, *agg = nullptr;
    cudaGetSymbolAddress((void**)&feats, g_feats);
    cudaGetSymbolAddress((void**)&x1,    g_x1);
    cudaGetSymbolAddress((void**)&bufA,  g_bufA);
    cudaGetSymbolAddress((void**)&bufB,  g_bufB);
    cudaGetSymbolAddress((void**)&agg,   g_agg);

    const int total = N_NODE * NDIM;
    build_feats_kernel<<<(total + 255) / 256, 256>>>(a, v, l, qmask, spk);

    dim3 gemm_grid(NHID / 128, N_NODE / 128);   // (4, 120)
    dim3 agg_grid(D_DIA, NHID / 128);           // (128, 4)

    // x1 = feats @ fc1_W + fc1_b
    sgemm_kernel<<<gemm_grid, 256>>>(feats, fc1_W, fc1_b, nullptr, x1);

    // gnn = x1; for k in 0..3: gnn = gnn + agg(gnn) @ Wk + bk
    const float* cur = x1;
    float* nxt[4] = {bufA, bufB, bufA, bufB};
    for (int k = 0; k < NUM_K; k++) {
        agg_kernel<<<agg_grid, 128>>>(cur, agg);
        sgemm_kernel<<<gemm_grid, 256>>>(agg,
                                         convW + (size_t)k * NHID * NHID,
                                         convb + (size_t)k * NHID,
                                         cur, nxt[k]);
        cur = nxt[k];
    }

    assemble_kernel<<<(total + 255) / 256, 256>>>(feats, x1, cur, out);
    (void)in_sizes; (void)n_in; (void)out_size;
}

// round 4
// speedup vs baseline: 2.8845x; 2.8845x over previous
#include <cuda_runtime.h>
#include <cuda_bf16.h>
#include <cstdint>

// Problem constants
#define D_DIA   128
#define L_DIA   40
#define NDIM    512
#define NHID    512
#define NUM_K   4
#define N_UTT   (D_DIA * L_DIA)        // 5120
#define N_NODE  (3 * N_UTT)            // 15360
#define ROWS_PER_DIA (3 * L_DIA)       // 120
#define OUT_D2  (NDIM + 2 * NHID)      // 1536
#define OUT_COLS (3 * OUT_D2)          // 4608

// GEMM config (mma.sync bf16, 3 fused precision passes)
#define BM 128
#define BN 128
#define BK 32                          // bf16 elems per k-tile (64 bytes)
#define KT_PER_PASS (NHID / BK)        // 16
#define KT_TOTAL (3 * KT_PER_PASS)     // 48
#define ROW_STRIDE 80                  // padded smem row stride (bytes) for 64B rows
#define TILE_BYTES (128 * ROW_STRIDE)  // 10240 per operand tile
#define STAGE_BYTES (2 * TILE_BYTES)   // 20480 (A + B)
#define STAGES 3
#define GEMM_SMEM_BYTES (STAGES * STAGE_BYTES)   // 61440

// ---------------------------------------------------------------------------
// Scratch (device globals; runtime allocation forbidden)
// ---------------------------------------------------------------------------
__device__ float g_feats[N_NODE * NDIM];
__device__ float g_x1   [N_NODE * NHID];
__device__ float g_bufA [N_NODE * NHID];
__device__ float g_bufB [N_NODE * NHID];
__device__ __nv_bfloat16 g_ahi[N_NODE * NHID];
__device__ __nv_bfloat16 g_alo[N_NODE * NHID];
__device__ __nv_bfloat16 g_wthi[5 * NHID * NHID];  // W^T: [w][n][k]
__device__ __nv_bfloat16 g_wtlo[5 * NHID * NHID];

// ---------------------------------------------------------------------------
// PTX helpers
// ---------------------------------------------------------------------------
__device__ __forceinline__ uint32_t smem_u32(const void* p) {
    uint32_t a;
    asm("{ .reg .u64 t; cvta.to.shared.u64 t, %1; cvt.u32.u64 %0, t; }" : "=r"(a) : "l"(p));
    return a;
}
__device__ __forceinline__ void cp16(uint32_t d, const void* g) {
    asm volatile("cp.async.cg.shared.global [%0], [%1], 16;" :: "r"(d), "l"(g));
}
__device__ __forceinline__ void ldsm4(uint32_t* r, uint32_t addr) {
    asm volatile("ldmatrix.sync.aligned.m8n8.x4.shared.b16 {%0,%1,%2,%3}, [%4];"
        : "=r"(r[0]), "=r"(r[1]), "=r"(r[2]), "=r"(r[3]) : "r"(addr));
}
__device__ __forceinline__ void mma_bf16(float* d, const uint32_t* a, uint32_t b0, uint32_t b1) {
    asm volatile("mma.sync.aligned.m16n8k16.row.col.f32.bf16.bf16.f32 "
        "{%0,%1,%2,%3}, {%4,%5,%6,%7}, {%8,%9}, {%0,%1,%2,%3};"
        : "+f"(d[0]), "+f"(d[1]), "+f"(d[2]), "+f"(d[3])
        : "r"(a[0]), "r"(a[1]), "r"(a[2]), "r"(a[3]), "r"(b0), "r"(b1));
}

// ---------------------------------------------------------------------------
// Weight transpose + hi/lo bf16 split: Wt[w][n][k] = W[w][k][n]
// ---------------------------------------------------------------------------
__global__ void transpose_split_kernel(const float* __restrict__ fc1W,
                                       const float* __restrict__ convW)
{
    __shared__ float tile[32][33];
    int w = blockIdx.z;
    const float* W = (w == 0) ? fc1W : convW + (size_t)(w - 1) * NHID * NHID;
    int n0 = blockIdx.x * 32, k0 = blockIdx.y * 32;
    #pragma unroll
    for (int i = 0; i < 32; i += 8)
        tile[threadIdx.y + i][threadIdx.x] = W[(size_t)(k0 + threadIdx.y + i) * NHID + n0 + threadIdx.x];
    __syncthreads();
    #pragma unroll
    for (int i = 0; i < 32; i += 8) {
        float v = tile[threadIdx.x][threadIdx.y + i];
        __nv_bfloat16 h = __float2bfloat16(v);
        size_t o = (size_t)w * NHID * NHID + (size_t)(n0 + threadIdx.y + i) * NHID + k0 + threadIdx.x;
        g_wthi[o] = h;
        g_wtlo[o] = __float2bfloat16(v - __bfloat162float(h));
    }
}

// ---------------------------------------------------------------------------
// Build node features (fp32 for assemble) + bf16 hi/lo split (GEMM A input)
// ---------------------------------------------------------------------------
__global__ void build_feats_kernel(const float* __restrict__ a,
                                   const float* __restrict__ v,
                                   const float* __restrict__ l,
                                   const float* __restrict__ qmask,
                                   const float* __restrict__ spk)
{
    int idx = blockIdx.x * blockDim.x + threadIdx.x;
    if (idx >= N_NODE * NDIM) return;
    int c    = idx & (NDIM - 1);
    int node = idx >> 9;
    int dia  = node / ROWS_PER_DIA;
    int r    = node - dia * ROWS_PER_DIA;
    int m    = r / L_DIA;
    int t    = r - m * L_DIA;
    int u    = dia * L_DIA + t;

    float val;
    if (m == 0) {
        float q0 = qmask[(t * D_DIA + dia) * 2 + 0];
        float q1 = qmask[(t * D_DIA + dia) * 2 + 1];
        int s = (q1 > q0) ? 1 : 0;
        val = l[u * NDIM + c] + spk[s * NDIM + c];
    } else if (m == 1) {
        val = a[u * NDIM + c];
    } else {
        val = v[u * NDIM + c];
    }
    g_feats[idx] = val;
    __nv_bfloat16 h = __float2bfloat16(val);
    g_ahi[idx] = h;
    g_alo[idx] = __float2bfloat16(val - __bfloat162float(h));
}

// ---------------------------------------------------------------------------
// Closed-form GCN aggregation fused with bf16 hi/lo split:
//   agg[dia,m,t] = (S[dia,m] + T[dia,t] - x[dia,m,t]) / 42
// ---------------------------------------------------------------------------
__global__ void agg_convert_kernel(const float* __restrict__ x)
{
    int dia = blockIdx.x;
    int c   = blockIdx.y * 128 + threadIdx.x;
    const float* xb = x + (size_t)dia * ROWS_PER_DIA * NHID;
    size_t ob = (size_t)dia * ROWS_PER_DIA * NHID;

    float S0 = 0.f, S1 = 0.f, S2 = 0.f;
    #pragma unroll 4
    for (int t = 0; t < L_DIA; t++) S0 += xb[t * NHID + c];
    #pragma unroll 4
    for (int t = 0; t < L_DIA; t++) S1 += xb[(L_DIA + t) * NHID + c];
    #pragma unroll 4
    for (int t = 0; t < L_DIA; t++) S2 += xb[(2 * L_DIA + t) * NHID + c];

    const float inv = 1.0f / 42.0f;
    for (int t = 0; t < L_DIA; t++) {
        float x0 = xb[t * NHID + c];
        float x1 = xb[(L_DIA + t) * NHID + c];
        float x2 = xb[(2 * L_DIA + t) * NHID + c];
        float T = x0 + x1 + x2;
        float v0 = (S0 + T - x0) * inv;
        float v1 = (S1 + T - x1) * inv;
        float v2 = (S2 + T - x2) * inv;
        size_t o0 = ob + (size_t)t * NHID + c;
        size_t o1 = ob + (size_t)(L_DIA + t) * NHID + c;
        size_t o2 = ob + (size_t)(2 * L_DIA + t) * NHID + c;
        __nv_bfloat16 h0 = __float2bfloat16(v0);
        __nv_bfloat16 h1 = __float2bfloat16(v1);
        __nv_bfloat16 h2 = __float2bfloat16(v2);
        g_ahi[o0] = h0; g_alo[o0] = __float2bfloat16(v0 - __bfloat162float(h0));
        g_ahi[o1] = h1; g_alo[o1] = __float2bfloat16(v1 - __bfloat162float(h1));
        g_ahi[o2] = h2; g_alo[o2] = __float2bfloat16(v2 - __bfloat162float(h2));
    }
}

// ---------------------------------------------------------------------------
// mma.sync bf16x3 GEMM: C[m,n] = sum_k A[m,k]*W[k,n] + bias[n] (+ P[m,n])
// A: hi/lo bf16 [M,512] row-major (g_ahi/g_alo); B: W^T hi/lo [512n][512k].
// Virtual K = 1536: pass0 Ahi*Bhi, pass1 Ahi*Blo, pass2 Alo*Bhi.
// ---------------------------------------------------------------------------
__global__ __launch_bounds__(256, 2)
void gemm_bf16x3_kernel(const __nv_bfloat16* __restrict__ Bhi,
                        const __nv_bfloat16* __restrict__ Blo,
                        const float* __restrict__ bias,
                        const float* __restrict__ P,
                        float* __restrict__ C)
{
    extern __shared__ char smem[];
    const uint32_t smem0 = smem_u32(smem);

    const int tid  = threadIdx.x;
    const int lane = tid & 31;
    const int wid  = tid >> 5;
    const int warp_m = wid & 3;        // 0..3 -> 32-row slab
    const int warp_n = wid >> 2;       // 0..1 -> 64-col slab
    const int bm = blockIdx.y * BM;
    const int bn = blockIdx.x * BN;

    float acc[2][8][4];
    #pragma unroll
    for (int i = 0; i < 2; i++)
        #pragma unroll
        for (int j = 0; j < 8; j++)
            #pragma unroll
            for (int q = 0; q < 4; q++) acc[i][j][q] = 0.f;

    // ldmatrix base addresses (stage 0, k16=0)
    const uint32_t aBase = smem0 + (uint32_t)(warp_m * 32 + (lane & 15)) * ROW_STRIDE
                         + (uint32_t)(lane >> 4) * 16;
    const uint32_t bBase = smem0 + TILE_BYTES
                         + (uint32_t)(warp_n * 64 + (lane & 15)) * ROW_STRIDE
                         + (uint32_t)(lane >> 4) * 16;

    const char* AhiP = (const char*)g_ahi;
    const char* AloP = (const char*)g_alo;
    const char* BhiP = (const char*)Bhi;
    const char* BloP = (const char*)Blo;

    auto load_tile = [&](int kt, int s) {
        int p = kt >> 4;
        const char* Ag = ((p < 2) ? AhiP : AloP) + (size_t)bm * 1024 + (kt & 15) * 64;
        const char* Bg = ((p == 1) ? BloP : BhiP) + (size_t)bn * 1024 + (kt & 15) * 64;
        uint32_t sa = smem0 + s * STAGE_BYTES;
        #pragma unroll
        for (int i = 0; i < 2; i++) {
            int ci  = i * 256 + tid;
            int row = ci >> 2;
            int cb  = (ci & 3) * 16;
            cp16(sa + row * ROW_STRIDE + cb, Ag + (size_t)row * 1024 + cb);
            cp16(sa + TILE_BYTES + row * ROW_STRIDE + cb, Bg + (size_t)row * 1024 + cb);
        }
        asm volatile("cp.async.commit_group;" ::: "memory");
    };

    // prologue: stages 0 and 1 in flight
    load_tile(0, 0);
    load_tile(1, 1);

    for (int kt = 0; kt < KT_TOTAL; kt++) {
        int s = kt % STAGES;
        asm volatile("cp.async.wait_group 1;" ::: "memory");
        __syncthreads();
        // keep one commit-group per iteration so wait_group 1 stays aligned
        if (kt + 2 < KT_TOTAL) load_tile(kt + 2, (kt + 2) % STAGES);
        else asm volatile("cp.async.commit_group;" ::: "memory");

        uint32_t sb = (uint32_t)s * STAGE_BYTES;
        #pragma unroll
        for (int k16 = 0; k16 < 2; k16++) {
            uint32_t a0[4], a1[4];
            ldsm4(a0, aBase + sb + k16 * 32);
            ldsm4(a1, aBase + sb + k16 * 32 + 16 * ROW_STRIDE);
            #pragma unroll
            for (int q = 0; q < 4; q++) {
                uint32_t b[4];
                ldsm4(b, bBase + sb + k16 * 32 + q * 16 * ROW_STRIDE);
                mma_bf16(acc[0][2 * q + 0], a0, b[0], b[2]);
                mma_bf16(acc[0][2 * q + 1], a0, b[1], b[3]);
                mma_bf16(acc[1][2 * q + 0], a1, b[0], b[2]);
                mma_bf16(acc[1][2 * q + 1], a1, b[1], b[3]);
            }
        }
    }

    // Epilogue: bias + optional residual, direct stores
    const bool hasP = (P != nullptr);
    const int m0 = bm + warp_m * 32;
    const int n0 = bn + warp_n * 64;
    #pragma unroll
    for (int mt = 0; mt < 2; mt++) {
        int r0 = m0 + mt * 16 + (lane >> 2);
        #pragma unroll
        for (int nt = 0; nt < 8; nt++) {
            int col = n0 + nt * 8 + (lane & 3) * 2;
            float bx = bias[col], by = bias[col + 1];
            size_t o0 = (size_t)r0 * NHID + col;
            size_t o1 = (size_t)(r0 + 8) * NHID + col;
            float2 v0 = make_float2(acc[mt][nt][0] + bx, acc[mt][nt][1] + by);
            float2 v1 = make_float2(acc[mt][nt][2] + bx, acc[mt][nt][3] + by);
            if (hasP) {
                float2 p0 = *(const float2*)(P + o0);
                float2 p1 = *(const float2*)(P + o1);
                v0.x += p0.x; v0.y += p0.y;
                v1.x += p1.x; v1.y += p1.y;
            }
            *(float2*)(C + o0) = v0;
            *(float2*)(C + o1) = v1;
        }
    }
}

// ---------------------------------------------------------------------------
// Assemble output: out[u, m*1536 + {feats|x1|gnn}]
// ---------------------------------------------------------------------------
__global__ void assemble_kernel(const float* __restrict__ gnn, float* __restrict__ out)
{
    int idx = blockIdx.x * blockDim.x + threadIdx.x;
    if (idx >= N_NODE * NDIM) return;
    int c    = idx & (NDIM - 1);
    int node = idx >> 9;
    int dia  = node / ROWS_PER_DIA;
    int r    = node - dia * ROWS_PER_DIA;
    int m    = r / L_DIA;
    int t    = r - m * L_DIA;
    int u    = dia * L_DIA + t;

    float* o = out + (size_t)u * OUT_COLS + m * OUT_D2 + c;
    o[0]        = g_feats[idx];
    o[NDIM]     = g_x1[idx];
    o[2 * NHID] = gnn[idx];
}

// ---------------------------------------------------------------------------
extern "C" void kernel_launch(void* const* d_in, const int* in_sizes, int n_in,
                              void* d_out, int out_size)
{
    const float* a      = (const float*)d_in[0];
    const float* v      = (const float*)d_in[1];
    const float* l      = (const float*)d_in[2];
    const float* qmask  = (const float*)d_in[3];
    const float* spk    = (const float*)d_in[4];
    const float* fc1_W  = (const float*)d_in[5];
    const float* fc1_b  = (const float*)d_in[6];
    const float* convW  = (const float*)d_in[7];
    const float* convb  = (const float*)d_in[8];
    float* out = (float*)d_out;

    float *x1 = nullptr, *bufA = nullptr, *bufB = nullptr;
    __nv_bfloat16 *wthi = nullptr, *wtlo = nullptr;
    cudaGetSymbolAddress((void**)&x1,   g_x1);
    cudaGetSymbolAddress((void**)&bufA, g_bufA);
    cudaGetSymbolAddress((void**)&bufB, g_bufB);
    cudaGetSymbolAddress((void**)&wthi, g_wthi);
    cudaGetSymbolAddress((void**)&wtlo, g_wtlo);

    cudaFuncSetAttribute(gemm_bf16x3_kernel,
                         cudaFuncAttributeMaxDynamicSharedMemorySize, GEMM_SMEM_BYTES);

    // 1. weights: transpose + bf16 split (w=0 fc1, w=1..4 conv)
    transpose_split_kernel<<<dim3(NHID / 32, NHID / 32, 5), dim3(32, 8)>>>(fc1_W, convW);

    // 2. features + bf16 split
    const int total = N_NODE * NDIM;
    build_feats_kernel<<<(total + 255) / 256, 256>>>(a, v, l, qmask, spk);

    dim3 gemm_grid(NHID / BN, N_NODE / BM);   // (4, 120)
    dim3 agg_grid(D_DIA, NHID / 128);         // (128, 4)

    // 3. x1 = feats @ fc1_W + fc1_b
    gemm_bf16x3_kernel<<<gemm_grid, 256, GEMM_SMEM_BYTES>>>(
        wthi, wtlo, fc1_b, nullptr, x1);

    // 4. gnn loop: gnn = gnn + agg(gnn) @ Wk + bk
    const float* cur = x1;
    float* nxt[4] = {bufA, bufB, bufA, bufB};
    for (int k = 0; k < NUM_K; k++) {
        agg_convert_kernel<<<agg_grid, 128>>>(cur);
        gemm_bf16x3_kernel<<<gemm_grid, 256, GEMM_SMEM_BYTES>>>(
            wthi + (size_t)(1 + k) * NHID * NHID,
            wtlo + (size_t)(1 + k) * NHID * NHID,
            convb + (size_t)k * NHID, cur, nxt[k]);
        cur = nxt[k];
    }

    // 5. assemble output
    assemble_kernel<<<(total + 255) / 256, 256>>>(cur, out);
    (void)in_sizes; (void)n_in; (void)out_size;
}